// round 15
// baseline (speedup 1.0000x reference)
#include <cuda_runtime.h>
#include <cuda_fp16.h>
#include <cstdint>

// Problem constants (fixed by the dataset)
#define S_LEN 2048
#define H_DIM 2048
#define NH    32
#define NKV   8
#define HD    64
#define QKV_COLS ((NH + 2*NKV) * HD)   // 3072

// ---------------------------------------------------------------------------
// Scratch (allocation-free rule: __device__ globals)
// ---------------------------------------------------------------------------
__device__ __align__(16) __half g_qkvh[(size_t)S_LEN * QKV_COLS]; // 12 MB
__device__ __align__(16) __half g_a[(size_t)S_LEN * H_DIM];       // 8 MB (x, then y)
__device__ __align__(16) __half g_b[(size_t)QKV_COLS * H_DIM];    // 12 MB (Wqkv)
__device__ __align__(16) __half g_c[(size_t)H_DIM * H_DIM];       // 8 MB (Wo)

// ---------------------------------------------------------------------------
// PTX helpers (sm_80+ ISA; tcgen05 rejected by plain-sm_103 ptxas)
// ---------------------------------------------------------------------------
__device__ __forceinline__ uint32_t smem_to_u32(const void* p) {
    uint32_t a;
    asm("{ .reg .u64 t; cvta.to.shared.u64 t, %1; cvt.u32.u64 %0, t; }"
        : "=r"(a) : "l"(p));
    return a;
}
__device__ __forceinline__ void cp_async16(uint32_t smem, const void* gptr) {
    asm volatile("cp.async.cg.shared.global [%0], [%1], 16;"
                 :: "r"(smem), "l"(__cvta_generic_to_global(gptr)) : "memory");
}
__device__ __forceinline__ void cp_commit() {
    asm volatile("cp.async.commit_group;" ::: "memory");
}
__device__ __forceinline__ void cp_wait1() {
    asm volatile("cp.async.wait_group 1;" ::: "memory");
}
__device__ __forceinline__ void ldsm4(uint32_t* r, uint32_t addr) {
    asm volatile("ldmatrix.sync.aligned.m8n8.x4.shared.b16 {%0,%1,%2,%3}, [%4];"
                 : "=r"(r[0]), "=r"(r[1]), "=r"(r[2]), "=r"(r[3]) : "r"(addr));
}
__device__ __forceinline__ void ldsm4t(uint32_t* r, uint32_t addr) {
    asm volatile("ldmatrix.sync.aligned.m8n8.x4.trans.shared.b16 {%0,%1,%2,%3}, [%4];"
                 : "=r"(r[0]), "=r"(r[1]), "=r"(r[2]), "=r"(r[3]) : "r"(addr));
}
__device__ __forceinline__ void mma16816f16(float* c, const uint32_t* a, const uint32_t* b) {
    asm volatile(
        "mma.sync.aligned.m16n8k16.row.col.f32.f16.f16.f32 "
        "{%0,%1,%2,%3}, {%4,%5,%6,%7}, {%8,%9}, {%0,%1,%2,%3};"
        : "+f"(c[0]), "+f"(c[1]), "+f"(c[2]), "+f"(c[3])
        : "r"(a[0]), "r"(a[1]), "r"(a[2]), "r"(a[3]), "r"(b[0]), "r"(b[1]));
}
__device__ __forceinline__ uint32_t pack_h2(float a, float b) {
    __half2 h = __floats2half2_rn(a, b);
    return *reinterpret_cast<uint32_t*>(&h);
}

// ---- packed f32x2 ops (Blackwell base ISA) ----
typedef unsigned long long u64;
__device__ __forceinline__ u64 pk2(float a, float b) {
    u64 r; asm("mov.b64 %0, {%1, %2};" : "=l"(r) : "f"(a), "f"(b)); return r;
}
__device__ __forceinline__ void upk2(u64 v, float& a, float& b) {
    asm("mov.b64 {%0, %1}, %2;" : "=f"(a), "=f"(b) : "l"(v));
}
__device__ __forceinline__ u64 add2_(u64 a, u64 b) {
    u64 r; asm("add.rn.f32x2 %0, %1, %2;" : "=l"(r) : "l"(a), "l"(b)); return r;
}
__device__ __forceinline__ u64 fma2_(u64 a, u64 b, u64 c) {
    u64 r; asm("fma.rn.f32x2 %0, %1, %2, %3;" : "=l"(r) : "l"(a), "l"(b), "l"(c)); return r;
}
__device__ __forceinline__ u64 dup2(float x) {
    unsigned int b = __float_as_uint(x);
    return ((u64)b << 32) | b;
}

// Scalar fast 2^d (clamped; per-pass rescale factor only).
__device__ __forceinline__ float fexp2(float d) {
    d = fmaxf(d, -80.0f);
    float t  = d + 12582912.0f;
    float nf = t - 12582912.0f;
    float f  = d - nf;
    int   n  = __float_as_int(t) - 0x4B400000;
    float p  = 9.6181291e-3f;
    p = fmaf(p, f, 5.5504108664e-2f);
    p = fmaf(p, f, 2.4022650696e-1f);
    p = fmaf(p, f, 6.9314718056e-1f);
    p = fmaf(p, f, 1.0f);
    return __int_as_float(__float_as_int(p) + (n << 23));
}

// Packed 2^(a0), 2^(a1); args in [-126, 0] (mask sentinel -500 guarantees).
#define FEXP2X2(arg, r0, r1) do {                                           \
    const u64 _kMAG  = dup2(12582912.0f);                                   \
    const u64 _kNEG1 = dup2(-1.0f);                                         \
    u64 _t  = add2_(arg, _kMAG);                                            \
    u64 _nf = add2_(_t, dup2(-12582912.0f));                                \
    u64 _f  = fma2_(_nf, _kNEG1, arg);                                      \
    u64 _p  = fma2_(dup2(9.6181291e-3f), _f, dup2(5.5504108664e-2f));       \
    _p = fma2_(_p, _f, dup2(2.4022650696e-1f));                             \
    _p = fma2_(_p, _f, dup2(6.9314718056e-1f));                             \
    _p = fma2_(_p, _f, dup2(1.0f));                                         \
    float _t0, _t1, _p0, _p1;                                               \
    upk2(_t, _t0, _t1);                                                     \
    upk2(_p, _p0, _p1);                                                     \
    int _n0 = (__float_as_int(_t0) - 0x4B400000) << 23;                     \
    int _n1 = (__float_as_int(_t1) - 0x4B400000) << 23;                     \
    r0 = __int_as_float(__float_as_int(_p0) + _n0);                         \
    r1 = __int_as_float(__float_as_int(_p1) + _n1);                         \
} while (0)

#if defined(__CUDA_ARCH__) && __CUDA_ARCH__ >= 900
#define GRID_DEP_SYNC() cudaGridDependencySynchronize()
#else
#define GRID_DEP_SYNC()
#endif

// ---------------------------------------------------------------------------
// fp32 -> fp16 convert for x + Wqkv only (Wo is converted in the flash tail).
// Streaming (evict-first) loads/stores.
// ---------------------------------------------------------------------------
#define N4_X  (S_LEN * H_DIM / 4)        // 1048576
#define N4_WQ (QKV_COLS * H_DIM / 4)     // 1572864
#define N4_WO (H_DIM * H_DIM / 4)        // 1048576
#define CVT2_BLOCKS ((N4_X + N4_WQ) / 1024)   // 2560

__global__ __launch_bounds__(256) void cvt_xwq_kernel(
    const float4* __restrict__ x, const float4* __restrict__ wq,
    uint2* __restrict__ ox, uint2* __restrict__ owq)
{
    const size_t base = (size_t)blockIdx.x * 1024;
    const float4* in;
    uint2* out;
    size_t j0;
    if (base < N4_X) { in = x;  out = ox;  j0 = base; }
    else             { in = wq; out = owq; j0 = base - N4_X; }

    const size_t t = j0 + threadIdx.x;
    float4 f0 = __ldcs(in + t);
    float4 f1 = __ldcs(in + t + 256);
    float4 f2 = __ldcs(in + t + 512);
    float4 f3 = __ldcs(in + t + 768);
    __stcs(out + t,       make_uint2(pack_h2(f0.x, f0.y), pack_h2(f0.z, f0.w)));
    __stcs(out + t + 256, make_uint2(pack_h2(f1.x, f1.y), pack_h2(f1.z, f1.w)));
    __stcs(out + t + 512, make_uint2(pack_h2(f2.x, f2.y), pack_h2(f2.z, f2.w)));
    __stcs(out + t + 768, make_uint2(pack_h2(f3.x, f3.y), pack_h2(f3.z, f3.w)));
}

// ---------------------------------------------------------------------------
// HMMA TN GEMM, fp16 in, templated output (fp32/fp16) + optional fused RoPE.
// CTA 128x128, BK=64, 3-stage cp.async pipeline. Validated R9/R10 mainloop.
// ---------------------------------------------------------------------------
#define HM_ROWB   144
#define HM_TILE_B (128 * HM_ROWB)            // 18432 B
#define HM_STAGE  (2 * HM_TILE_B)            // 36864 B
#define HM_SMEM   (3 * HM_STAGE)             // 110592 B

template <bool HALF_OUT, bool ROPE>
__global__ __launch_bounds__(256, 2) void hgemm_kernel(
    const __half* __restrict__ A, const __half* __restrict__ B,
    void* __restrict__ Cv, const float* __restrict__ fc, int M, int N, int K)
{
    GRID_DEP_SYNC();                     // PDL: wait for producer grid

    extern __shared__ char smem[];
    const uint32_t sbase = smem_to_u32(smem);

    const int tid  = threadIdx.x;
    const int wid  = tid >> 5;
    const int lane = tid & 31;
    const int warpM = wid >> 1;
    const int warpN = wid & 1;
    const int bm = blockIdx.y * 128;
    const int bn = blockIdx.x * 128;

    const int ldrow = tid >> 3;
    const int ldch  = (tid & 7) * 16;
    const __half* gA0 = A + (size_t)(bm + ldrow) * K + (ldch >> 1);
    const __half* gB0 = B + (size_t)(bn + ldrow) * K + (ldch >> 1);

    const uint32_t aAddrBase =
        (uint32_t)(warpM * 32 + (lane & 15)) * HM_ROWB + (lane >> 4) * 16;
    const uint32_t bAddrBase =
        (uint32_t)(warpN * 64 + ((lane >> 4) & 1) * 8 + (lane & 7)) * HM_ROWB
        + ((lane >> 3) & 1) * 16;

    float acc[2][8][4];
#pragma unroll
    for (int m = 0; m < 2; m++)
#pragma unroll
        for (int n = 0; n < 8; n++)
#pragma unroll
            for (int q = 0; q < 4; q++) acc[m][n][q] = 0.f;

    const int nchunk = K / 64;

    auto load_stage = [&](int s, int c) {
        const uint32_t st = sbase + s * HM_STAGE;
        const int k0 = c * 64;
#pragma unroll
        for (int i = 0; i < 4; i++) {
            const uint32_t so = (uint32_t)(ldrow + 32 * i) * HM_ROWB + ldch;
            cp_async16(st + so, gA0 + (size_t)(32 * i) * K + k0);
            cp_async16(st + HM_TILE_B + so, gB0 + (size_t)(32 * i) * K + k0);
        }
    };

    load_stage(0, 0); cp_commit();
    load_stage(1, 1); cp_commit();

    int s = 0;
    for (int c = 0; c < nchunk; c++) {
        cp_wait1();
        __syncthreads();
        {
            int s2 = s + 2; if (s2 >= 3) s2 -= 3;
            if (c + 2 < nchunk) load_stage(s2, c + 2);
            cp_commit();
        }

        const uint32_t st = sbase + s * HM_STAGE;
        const uint32_t sA = st + aAddrBase;
        const uint32_t sB = st + HM_TILE_B + bAddrBase;

#pragma unroll
        for (int ks = 0; ks < 4; ks++) {
            const uint32_t ko = ks * 32;
            uint32_t a[2][4];
            ldsm4(a[0], sA + ko);
            ldsm4(a[1], sA + 16 * HM_ROWB + ko);
            uint32_t b0[4], b1[4];
            ldsm4(b0, sB + ko);
#pragma unroll
            for (int p = 0; p < 4; p++) {
                uint32_t* bc = (p & 1) ? b1 : b0;
                uint32_t* bn2 = (p & 1) ? b0 : b1;
                if (p < 3)
                    ldsm4(bn2, sB + (uint32_t)(p + 1) * 16 * HM_ROWB + ko);
#pragma unroll
                for (int m = 0; m < 2; m++) {
                    mma16816f16(acc[m][2 * p + 0], a[m], bc + 0);
                    mma16816f16(acc[m][2 * p + 1], a[m], bc + 2);
                }
            }
        }
        if (++s == 3) s = 0;
    }

    // fused RoPE (uniform per CTA: q/k head cols are [0,2560), 128-aligned)
    if (ROPE && bn < NH * HD + NKV * HD) {
        const int d0 = lane & 3;
#pragma unroll
        for (int m = 0; m < 2; m++) {
            const int r0 = bm + warpM * 32 + m * 16 + (lane >> 2);
#pragma unroll
            for (int n = 0; n < 8; n++) {
                const int d = n * 4 + d0;
                float2 cs0 = *reinterpret_cast<const float2*>(fc + (size_t)r0 * 64 + d * 2);
                float2 cs1 = *reinterpret_cast<const float2*>(fc + (size_t)(r0 + 8) * 64 + d * 2);
                float x0 = acc[m][n][0], x1 = acc[m][n][1];
                acc[m][n][0] = x0 * cs0.x - x1 * cs0.y;
                acc[m][n][1] = x1 * cs0.x + x0 * cs0.y;
                float y0 = acc[m][n][2], y1 = acc[m][n][3];
                acc[m][n][2] = y0 * cs1.x - y1 * cs1.y;
                acc[m][n][3] = y1 * cs1.x + y0 * cs1.y;
            }
        }
    }

    const int qrow = lane >> 2;
    const int qcol = (lane & 3) * 2;
#pragma unroll
    for (int m = 0; m < 2; m++) {
        const int row0 = bm + warpM * 32 + m * 16 + qrow;
#pragma unroll
        for (int n = 0; n < 8; n++) {
            const int col = bn + warpN * 64 + n * 8 + qcol;
            if (HALF_OUT) {
                __half* C = (__half*)Cv;
                *reinterpret_cast<uint32_t*>(C + (size_t)row0 * N + col) =
                    pack_h2(acc[m][n][0], acc[m][n][1]);
                *reinterpret_cast<uint32_t*>(C + (size_t)(row0 + 8) * N + col) =
                    pack_h2(acc[m][n][2], acc[m][n][3]);
            } else {
                float* C = (float*)Cv;
                *reinterpret_cast<float2*>(C + (size_t)row0 * N + col) =
                    make_float2(acc[m][n][0], acc[m][n][1]);
                *reinterpret_cast<float2*>(C + (size_t)(row0 + 8) * N + col) =
                    make_float2(acc[m][n][2], acc[m][n][3]);
            }
        }
    }
}

// ---------------------------------------------------------------------------
// HMMA flash attention, causal, GQA. Q-tile 128 rows, KV-tile 64.
// 8 warps, warp owns 16 full rows (FA-2, warp-local softmax).
// 3 KV stages, ONE sync + ONE wait per tile. LPT (longest-first) 1D grid.
// Tail backfill: the last 128 CTAs (shortest attention tiles) each convert
// 1/128 of Wo fp32->fp16 after their tile — hidden in otherwise-idle slots.
// ---------------------------------------------------------------------------
#define FK_ROW  144
#define FK_TILE (64 * FK_ROW)
#define FQ_SZ   (128 * FK_ROW)
#define FK_STG  (2 * FK_TILE)
#define FK_SMEM (FQ_SZ + 3 * FK_STG)           // 73728 B
#define N_QT    (S_LEN / 128)                  // 16

__global__ __launch_bounds__(256, 2) void flash_hmma_kernel(
    const __half* __restrict__ qkvh, __half* __restrict__ Y,
    const float4* __restrict__ wo32, uint2* __restrict__ woh)
{
    GRID_DEP_SYNC();                     // PDL: wait for GEMM1 grid

    extern __shared__ char sm[];
    const uint32_t sb = smem_to_u32(sm);

    const int bx = blockIdx.x;
    const int qt = (N_QT - 1) - (bx >> 5);     // longest-first
    const int h  = bx & 31;
    const int kh = h >> 2;
    const int q0 = qt * 128;
    const int njt = 2 * qt + 2;

    const int tid  = threadIdx.x;
    const int w    = tid >> 5;
    const int lane = tid & 31;

    const float C2 = 0.18033688011112042f;   // (1/8) * log2(e)

    const uint32_t qAddr = (uint32_t)(w * 16 + (lane & 15)) * FK_ROW + (lane >> 4) * 16;
    const uint32_t kAddr = (uint32_t)(((lane >> 4) & 1) * 8 + (lane & 7)) * FK_ROW
                           + ((lane >> 3) & 1) * 16;
    const uint32_t vAddr = (uint32_t)((lane & 7) + ((lane >> 3) & 1) * 8) * FK_ROW
                           + (lane >> 4) * 16;

    auto load_q = [&]() {
#pragma unroll
        for (int i = 0; i < 4; i++) {
            int p = tid + i * 256, row = p >> 3, ch = p & 7;
            cp_async16(sb + (uint32_t)row * FK_ROW + ch * 16,
                       qkvh + (size_t)(q0 + row) * QKV_COLS + h * HD + ch * 8);
        }
    };
    auto load_kv = [&](int s, int jt) {
        const int j0 = jt * 64;
        const uint32_t Kb = sb + FQ_SZ + s * FK_STG;
#pragma unroll
        for (int i = 0; i < 2; i++) {
            int p = tid + i * 256, row = p >> 3, ch = p & 7;
            const __half* base = qkvh + (size_t)(j0 + row) * QKV_COLS + kh * HD + ch * 8;
            cp_async16(Kb + (uint32_t)row * FK_ROW + ch * 16, base + NH * HD);
            cp_async16(Kb + FK_TILE + (uint32_t)row * FK_ROW + ch * 16, base + (NH + NKV) * HD);
        }
    };

    load_q(); load_kv(0, 0); cp_commit();
    load_kv(1, 1); cp_commit();

    uint32_t aQ[4][4];
    float o[8][4];
#pragma unroll
    for (int n = 0; n < 8; n++)
#pragma unroll
        for (int q = 0; q < 4; q++) o[n][q] = 0.f;
    float m2[2] = { -1e30f, -1e30f };
    float l[2]  = { 0.f, 0.f };

    int s = 0;
    for (int jt = 0; jt < njt; jt++) {
        cp_wait1();
        __syncthreads();
        {
            int s2 = s + 2; if (s2 >= 3) s2 -= 3;
            if (jt + 2 < njt) load_kv(s2, jt + 2);
            cp_commit();
        }
        if (jt == 0) {
#pragma unroll
            for (int kc = 0; kc < 4; kc++) ldsm4(aQ[kc], sb + qAddr + kc * 32);
        }

        const uint32_t Kb = sb + FQ_SZ + s * FK_STG;
        const uint32_t Vb = Kb + FK_TILE;

        float sc[8][4];
#pragma unroll
        for (int n = 0; n < 8; n++)
#pragma unroll
            for (int q = 0; q < 4; q++) sc[n][q] = 0.f;
        {
            uint32_t b0[4], b1[4];
            ldsm4(b0, Kb + kAddr);
#pragma unroll
            for (int t = 0; t < 16; t++) {
                const int p = t >> 2, kc = t & 3;
                uint32_t* bc = (t & 1) ? b1 : b0;
                uint32_t* bn = (t & 1) ? b0 : b1;
                if (t < 15) {
                    const int t2 = t + 1;
                    ldsm4(bn, Kb + kAddr + (uint32_t)(t2 >> 2) * 16 * FK_ROW
                                         + (uint32_t)(t2 & 3) * 32);
                }
                mma16816f16(sc[2 * p + 0], aQ[kc], bc + 0);
                mma16816f16(sc[2 * p + 1], aQ[kc], bc + 2);
            }
        }

        if (jt >= 2 * qt) {
            const int j0 = jt * 64;
            const int rg = q0 + w * 16 + (lane >> 2);
            const int cb = j0 + (lane & 3) * 2;
#pragma unroll
            for (int n = 0; n < 8; n++) {
#pragma unroll
                for (int e = 0; e < 2; e++) {
                    int cg = cb + n * 8 + e;
                    if (cg > rg)     sc[n][e]     = -500.f;
                    if (cg > rg + 8) sc[n][e + 2] = -500.f;
                }
            }
        }

        uint32_t ph[8][2];
        {
            float mr[2], m2n[2], r[2], sum[2];
            u64 NM2[2];
#pragma unroll
            for (int i = 0; i < 2; i++) {
                float m_ = -1e30f;
#pragma unroll
                for (int n = 0; n < 8; n++)
                    m_ = fmaxf(m_, fmaxf(sc[n][2 * i], sc[n][2 * i + 1]));
                mr[i] = m_;
            }
#pragma unroll
            for (int i = 0; i < 2; i++)
                mr[i] = fmaxf(mr[i], __shfl_xor_sync(0xffffffffu, mr[i], 1));
#pragma unroll
            for (int i = 0; i < 2; i++)
                mr[i] = fmaxf(mr[i], __shfl_xor_sync(0xffffffffu, mr[i], 2));
#pragma unroll
            for (int i = 0; i < 2; i++) {
                m2n[i] = fmaxf(m2[i], mr[i] * C2);
                r[i]   = fexp2(m2[i] - m2n[i]);
                m2[i]  = m2n[i];
                NM2[i] = dup2(-m2n[i]);
                sum[i] = 0.f;
            }
            const u64 kSC = dup2(C2);
#pragma unroll
            for (int n = 0; n < 8; n++) {
#pragma unroll
                for (int i = 0; i < 2; i++) {
                    u64 s2  = pk2(sc[n][2 * i], sc[n][2 * i + 1]);
                    u64 arg = fma2_(s2, kSC, NM2[i]);
                    float p0, p1;
                    FEXP2X2(arg, p0, p1);
                    sum[i] += p0 + p1;
                    ph[n][i] = pack_h2(p0, p1);
                }
            }
#pragma unroll
            for (int i = 0; i < 2; i++)
                sum[i] += __shfl_xor_sync(0xffffffffu, sum[i], 1);
#pragma unroll
            for (int i = 0; i < 2; i++)
                sum[i] += __shfl_xor_sync(0xffffffffu, sum[i], 2);
#pragma unroll
            for (int i = 0; i < 2; i++)
                l[i] = l[i] * r[i] + sum[i];
#pragma unroll
            for (int n = 0; n < 8; n++) {
#pragma unroll
                for (int i = 0; i < 2; i++) {
                    o[n][2 * i]     *= r[i];
                    o[n][2 * i + 1] *= r[i];
                }
            }
        }

        {
            uint32_t b0[4], b1[4];
            ldsm4t(b0, Vb + vAddr);
#pragma unroll
            for (int t = 0; t < 16; t++) {
                const int kc = t >> 2, vp = t & 3;
                uint32_t* bc = (t & 1) ? b1 : b0;
                uint32_t* bn = (t & 1) ? b0 : b1;
                if (t < 15) {
                    const int t2 = t + 1;
                    ldsm4t(bn, Vb + vAddr + (uint32_t)(t2 >> 2) * 16 * FK_ROW
                                          + (uint32_t)(t2 & 3) * 32);
                }
                uint32_t a[4] = { ph[2 * kc][0], ph[2 * kc][1],
                                  ph[2 * kc + 1][0], ph[2 * kc + 1][1] };
                mma16816f16(o[2 * vp + 0], a, bc + 0);
                mma16816f16(o[2 * vp + 1], a, bc + 2);
            }
        }

        if (++s == 3) s = 0;
    }

    // epilogue: fp16 y
#pragma unroll
    for (int i = 0; i < 2; i++) {
        float inv = 1.f / l[i];
        int row = q0 + w * 16 + (lane >> 2) + 8 * i;
        __half* yr = Y + (size_t)row * H_DIM + h * HD + (lane & 3) * 2;
#pragma unroll
        for (int n = 0; n < 8; n++) {
            __half2 v = __floats2half2_rn(o[n][2 * i] * inv, o[n][2 * i + 1] * inv);
            *reinterpret_cast<__half2*>(yr + n * 8) = v;
        }
    }

    // --- tail backfill: last 128 CTAs (qt 0..3, shortest) convert Wo slices.
    // GEMM2's PDL grid-sync waits for this entire grid, so Wo is complete
    // before GEMM2 reads it.
    const int ci = bx - (N_QT * NH - 128);
    if (ci >= 0) {
        const float4* src = wo32 + (size_t)ci * 8192;
        uint2* dst = woh + (size_t)ci * 8192;
#pragma unroll 4
        for (int j = tid; j < 8192; j += 256) {
            float4 f = __ldcs(src + j);
            __stcs(dst + j, make_uint2(pack_h2(f.x, f.y), pack_h2(f.z, f.w)));
        }
    }
}

// ---------------------------------------------------------------------------
// kernel_launch: cvt(x,Wqkv) -> gemm1(+rope) -> flash(+Wo cvt) -> gemm2 (PDL)
// ---------------------------------------------------------------------------
template <typename F, typename... Args>
static inline void launch_pdl(F func, dim3 grid, dim3 block, size_t smem,
                              Args... args)
{
    cudaLaunchConfig_t cfg = {};
    cfg.gridDim = grid;
    cfg.blockDim = block;
    cfg.dynamicSmemBytes = smem;
    cfg.stream = 0;
    cudaLaunchAttribute attr[1];
    attr[0].id = cudaLaunchAttributeProgrammaticStreamSerialization;
    attr[0].val.programmaticStreamSerializationAllowed = 1;
    cfg.attrs = attr;
    cfg.numAttrs = 1;
    cudaLaunchKernelEx(&cfg, func, args...);
}

extern "C" void kernel_launch(void* const* d_in, const int* in_sizes, int n_in,
                              void* d_out, int out_size)
{
    const float* x    = (const float*)d_in[0];
    const float* fc   = (const float*)d_in[1];
    const float* Wqkv = (const float*)d_in[3];
    const float* Wo   = (const float*)d_in[4];
    float* out = (float*)d_out;

    __half *qkvh, *ga, *gb, *gc;
    cudaGetSymbolAddress((void**)&qkvh, g_qkvh);
    cudaGetSymbolAddress((void**)&ga, g_a);
    cudaGetSymbolAddress((void**)&gb, g_b);
    cudaGetSymbolAddress((void**)&gc, g_c);

    cudaFuncSetAttribute((const void*)hgemm_kernel<true, true>,
                         cudaFuncAttributeMaxDynamicSharedMemorySize, HM_SMEM);
    cudaFuncSetAttribute((const void*)hgemm_kernel<false, false>,
                         cudaFuncAttributeMaxDynamicSharedMemorySize, HM_SMEM);
    cudaFuncSetAttribute((const void*)flash_hmma_kernel,
                         cudaFuncAttributeMaxDynamicSharedMemorySize, FK_SMEM);

    // 1) convert x + Wqkv to fp16 (streaming); Wo deferred to flash tail
    cvt_xwq_kernel<<<CVT2_BLOCKS, 256>>>(
        (const float4*)x, (const float4*)Wqkv, (uint2*)ga, (uint2*)gb);

    // 2) QKV projection with fused RoPE, fp16 output (PDL after cvt)
    launch_pdl(hgemm_kernel<true, true>,
               dim3(QKV_COLS / 128, S_LEN / 128), dim3(256), HM_SMEM,
               (const __half*)ga, (const __half*)gb, (void*)qkvh,
               (const float*)fc, (int)S_LEN, (int)QKV_COLS, (int)H_DIM);

    // 3) flash attention (LPT) + Wo conversion in the tail (PDL after gemm1)
    launch_pdl(flash_hmma_kernel, dim3(N_QT * NH), dim3(256), (size_t)FK_SMEM,
               (const __half*)qkvh, (__half*)ga,
               (const float4*)Wo, (uint2*)gc);

    // 4) output projection, fp32 output (PDL after flash)
    launch_pdl(hgemm_kernel<false, false>,
               dim3(H_DIM / 128, S_LEN / 128), dim3(256), HM_SMEM,
               (const __half*)ga, (const __half*)gc, (void*)out,
               (const float*)nullptr, (int)S_LEN, (int)H_DIM, (int)H_DIM);
}

// round 16
// speedup vs baseline: 1.0531x; 1.0531x over previous
#include <cuda_runtime.h>
#include <cuda_fp16.h>
#include <cstdint>

// Problem constants (fixed by the dataset)
#define S_LEN 2048
#define H_DIM 2048
#define NH    32
#define NKV   8
#define HD    64
#define QKV_COLS ((NH + 2*NKV) * HD)   // 3072

// ---------------------------------------------------------------------------
// Scratch (allocation-free rule: __device__ globals)
// ---------------------------------------------------------------------------
__device__ __align__(16) __half g_qkvh[(size_t)S_LEN * QKV_COLS]; // 12 MB
__device__ __align__(16) __half g_a[(size_t)S_LEN * H_DIM];       // 8 MB (x, then y)
__device__ __align__(16) __half g_b[(size_t)QKV_COLS * H_DIM];    // 12 MB (Wqkv)
__device__ __align__(16) __half g_c[(size_t)H_DIM * H_DIM];       // 8 MB (Wo)

// ---------------------------------------------------------------------------
// PTX helpers (sm_80+ ISA; tcgen05 rejected by plain-sm_103 ptxas)
// ---------------------------------------------------------------------------
__device__ __forceinline__ uint32_t smem_to_u32(const void* p) {
    uint32_t a;
    asm("{ .reg .u64 t; cvta.to.shared.u64 t, %1; cvt.u32.u64 %0, t; }"
        : "=r"(a) : "l"(p));
    return a;
}
__device__ __forceinline__ void cp_async16(uint32_t smem, const void* gptr) {
    asm volatile("cp.async.cg.shared.global [%0], [%1], 16;"
                 :: "r"(smem), "l"(__cvta_generic_to_global(gptr)) : "memory");
}
__device__ __forceinline__ void cp_commit() {
    asm volatile("cp.async.commit_group;" ::: "memory");
}
__device__ __forceinline__ void cp_wait1() {
    asm volatile("cp.async.wait_group 1;" ::: "memory");
}
__device__ __forceinline__ void cp_wait2() {
    asm volatile("cp.async.wait_group 2;" ::: "memory");
}
__device__ __forceinline__ void ldsm4(uint32_t* r, uint32_t addr) {
    asm volatile("ldmatrix.sync.aligned.m8n8.x4.shared.b16 {%0,%1,%2,%3}, [%4];"
                 : "=r"(r[0]), "=r"(r[1]), "=r"(r[2]), "=r"(r[3]) : "r"(addr));
}
__device__ __forceinline__ void ldsm4t(uint32_t* r, uint32_t addr) {
    asm volatile("ldmatrix.sync.aligned.m8n8.x4.trans.shared.b16 {%0,%1,%2,%3}, [%4];"
                 : "=r"(r[0]), "=r"(r[1]), "=r"(r[2]), "=r"(r[3]) : "r"(addr));
}
__device__ __forceinline__ void mma16816f16(float* c, const uint32_t* a, const uint32_t* b) {
    asm volatile(
        "mma.sync.aligned.m16n8k16.row.col.f32.f16.f16.f32 "
        "{%0,%1,%2,%3}, {%4,%5,%6,%7}, {%8,%9}, {%0,%1,%2,%3};"
        : "+f"(c[0]), "+f"(c[1]), "+f"(c[2]), "+f"(c[3])
        : "r"(a[0]), "r"(a[1]), "r"(a[2]), "r"(a[3]), "r"(b[0]), "r"(b[1]));
}
__device__ __forceinline__ uint32_t pack_h2(float a, float b) {
    __half2 h = __floats2half2_rn(a, b);
    return *reinterpret_cast<uint32_t*>(&h);
}

// ---- packed f32x2 ops (Blackwell base ISA) ----
typedef unsigned long long u64;
__device__ __forceinline__ u64 pk2(float a, float b) {
    u64 r; asm("mov.b64 %0, {%1, %2};" : "=l"(r) : "f"(a), "f"(b)); return r;
}
__device__ __forceinline__ void upk2(u64 v, float& a, float& b) {
    asm("mov.b64 {%0, %1}, %2;" : "=f"(a), "=f"(b) : "l"(v));
}
__device__ __forceinline__ u64 add2_(u64 a, u64 b) {
    u64 r; asm("add.rn.f32x2 %0, %1, %2;" : "=l"(r) : "l"(a), "l"(b)); return r;
}
__device__ __forceinline__ u64 fma2_(u64 a, u64 b, u64 c) {
    u64 r; asm("fma.rn.f32x2 %0, %1, %2, %3;" : "=l"(r) : "l"(a), "l"(b), "l"(c)); return r;
}
__device__ __forceinline__ u64 dup2(float x) {
    unsigned int b = __float_as_uint(x);
    return ((u64)b << 32) | b;
}

// Scalar fast 2^d (clamped; per-pass rescale factor only).
__device__ __forceinline__ float fexp2(float d) {
    d = fmaxf(d, -80.0f);
    float t  = d + 12582912.0f;
    float nf = t - 12582912.0f;
    float f  = d - nf;
    int   n  = __float_as_int(t) - 0x4B400000;
    float p  = 9.6181291e-3f;
    p = fmaf(p, f, 5.5504108664e-2f);
    p = fmaf(p, f, 2.4022650696e-1f);
    p = fmaf(p, f, 6.9314718056e-1f);
    p = fmaf(p, f, 1.0f);
    return __int_as_float(__float_as_int(p) + (n << 23));
}

// Packed 2^(a0), 2^(a1); args in [-126, 0] (mask sentinel -500 guarantees).
#define FEXP2X2(arg, r0, r1) do {                                           \
    const u64 _kMAG  = dup2(12582912.0f);                                   \
    const u64 _kNEG1 = dup2(-1.0f);                                         \
    u64 _t  = add2_(arg, _kMAG);                                            \
    u64 _nf = add2_(_t, dup2(-12582912.0f));                                \
    u64 _f  = fma2_(_nf, _kNEG1, arg);                                      \
    u64 _p  = fma2_(dup2(9.6181291e-3f), _f, dup2(5.5504108664e-2f));       \
    _p = fma2_(_p, _f, dup2(2.4022650696e-1f));                             \
    _p = fma2_(_p, _f, dup2(6.9314718056e-1f));                             \
    _p = fma2_(_p, _f, dup2(1.0f));                                         \
    float _t0, _t1, _p0, _p1;                                               \
    upk2(_t, _t0, _t1);                                                     \
    upk2(_p, _p0, _p1);                                                     \
    int _n0 = (__float_as_int(_t0) - 0x4B400000) << 23;                     \
    int _n1 = (__float_as_int(_t1) - 0x4B400000) << 23;                     \
    r0 = __int_as_float(__float_as_int(_p0) + _n0);                         \
    r1 = __int_as_float(__float_as_int(_p1) + _n1);                         \
} while (0)

#if defined(__CUDA_ARCH__) && __CUDA_ARCH__ >= 900
#define GRID_DEP_SYNC() cudaGridDependencySynchronize()
#else
#define GRID_DEP_SYNC()
#endif

// ---------------------------------------------------------------------------
// Fused fp32 -> fp16 convert for x, Wqkv, Wo. Streaming (evict-first).
// ---------------------------------------------------------------------------
#define N4_X  (S_LEN * H_DIM / 4)
#define N4_WQ (QKV_COLS * H_DIM / 4)
#define N4_WO (H_DIM * H_DIM / 4)
#define N4_ALL (N4_X + N4_WQ + N4_WO)
#define CVT_BLOCKS (N4_ALL / 1024)

__global__ __launch_bounds__(256) void cvt_all_kernel(
    const float4* __restrict__ x, const float4* __restrict__ wq,
    const float4* __restrict__ wo,
    uint2* __restrict__ ox, uint2* __restrict__ owq, uint2* __restrict__ owo)
{
    const size_t base = (size_t)blockIdx.x * 1024;
    const float4* in;
    uint2* out;
    size_t j0;
    if (base < N4_X)                      { in = x;  out = ox;  j0 = base; }
    else if (base < (size_t)N4_X + N4_WQ) { in = wq; out = owq; j0 = base - N4_X; }
    else                                  { in = wo; out = owo; j0 = base - N4_X - N4_WQ; }

    const size_t t = j0 + threadIdx.x;
    float4 f0 = __ldcs(in + t);
    float4 f1 = __ldcs(in + t + 256);
    float4 f2 = __ldcs(in + t + 512);
    float4 f3 = __ldcs(in + t + 768);
    __stcs(out + t,       make_uint2(pack_h2(f0.x, f0.y), pack_h2(f0.z, f0.w)));
    __stcs(out + t + 256, make_uint2(pack_h2(f1.x, f1.y), pack_h2(f1.z, f1.w)));
    __stcs(out + t + 512, make_uint2(pack_h2(f2.x, f2.y), pack_h2(f2.z, f2.w)));
    __stcs(out + t + 768, make_uint2(pack_h2(f3.x, f3.y), pack_h2(f3.z, f3.w)));
}

// ---------------------------------------------------------------------------
// HMMA TN GEMM, fp16 in, templated output (fp32/fp16) + optional fused RoPE.
// CTA 128x128, BK=64, 3-stage cp.async pipeline. Validated R9/R10 mainloop.
// ---------------------------------------------------------------------------
#define HM_ROWB   144
#define HM_TILE_B (128 * HM_ROWB)            // 18432 B
#define HM_STAGE  (2 * HM_TILE_B)            // 36864 B
#define HM_SMEM   (3 * HM_STAGE)             // 110592 B

template <bool HALF_OUT, bool ROPE>
__global__ __launch_bounds__(256, 2) void hgemm_kernel(
    const __half* __restrict__ A, const __half* __restrict__ B,
    void* __restrict__ Cv, const float* __restrict__ fc, int M, int N, int K)
{
    GRID_DEP_SYNC();                     // PDL: wait for producer grid

    extern __shared__ char smem[];
    const uint32_t sbase = smem_to_u32(smem);

    const int tid  = threadIdx.x;
    const int wid  = tid >> 5;
    const int lane = tid & 31;
    const int warpM = wid >> 1;
    const int warpN = wid & 1;
    const int bm = blockIdx.y * 128;
    const int bn = blockIdx.x * 128;

    const int ldrow = tid >> 3;
    const int ldch  = (tid & 7) * 16;
    const __half* gA0 = A + (size_t)(bm + ldrow) * K + (ldch >> 1);
    const __half* gB0 = B + (size_t)(bn + ldrow) * K + (ldch >> 1);

    const uint32_t aAddrBase =
        (uint32_t)(warpM * 32 + (lane & 15)) * HM_ROWB + (lane >> 4) * 16;
    const uint32_t bAddrBase =
        (uint32_t)(warpN * 64 + ((lane >> 4) & 1) * 8 + (lane & 7)) * HM_ROWB
        + ((lane >> 3) & 1) * 16;

    float acc[2][8][4];
#pragma unroll
    for (int m = 0; m < 2; m++)
#pragma unroll
        for (int n = 0; n < 8; n++)
#pragma unroll
            for (int q = 0; q < 4; q++) acc[m][n][q] = 0.f;

    const int nchunk = K / 64;

    auto load_stage = [&](int s, int c) {
        const uint32_t st = sbase + s * HM_STAGE;
        const int k0 = c * 64;
#pragma unroll
        for (int i = 0; i < 4; i++) {
            const uint32_t so = (uint32_t)(ldrow + 32 * i) * HM_ROWB + ldch;
            cp_async16(st + so, gA0 + (size_t)(32 * i) * K + k0);
            cp_async16(st + HM_TILE_B + so, gB0 + (size_t)(32 * i) * K + k0);
        }
    };

    load_stage(0, 0); cp_commit();
    load_stage(1, 1); cp_commit();

    int s = 0;
    for (int c = 0; c < nchunk; c++) {
        cp_wait1();
        __syncthreads();
        {
            int s2 = s + 2; if (s2 >= 3) s2 -= 3;
            if (c + 2 < nchunk) load_stage(s2, c + 2);
            cp_commit();
        }

        const uint32_t st = sbase + s * HM_STAGE;
        const uint32_t sA = st + aAddrBase;
        const uint32_t sB = st + HM_TILE_B + bAddrBase;

#pragma unroll
        for (int ks = 0; ks < 4; ks++) {
            const uint32_t ko = ks * 32;
            uint32_t a[2][4];
            ldsm4(a[0], sA + ko);
            ldsm4(a[1], sA + 16 * HM_ROWB + ko);
            uint32_t b0[4], b1[4];
            ldsm4(b0, sB + ko);
#pragma unroll
            for (int p = 0; p < 4; p++) {
                uint32_t* bc = (p & 1) ? b1 : b0;
                uint32_t* bn2 = (p & 1) ? b0 : b1;
                if (p < 3)
                    ldsm4(bn2, sB + (uint32_t)(p + 1) * 16 * HM_ROWB + ko);
#pragma unroll
                for (int m = 0; m < 2; m++) {
                    mma16816f16(acc[m][2 * p + 0], a[m], bc + 0);
                    mma16816f16(acc[m][2 * p + 1], a[m], bc + 2);
                }
            }
        }
        if (++s == 3) s = 0;
    }

    // fused RoPE (uniform per CTA: q/k head cols are [0,2560), 128-aligned)
    if (ROPE && bn < NH * HD + NKV * HD) {
        const int d0 = lane & 3;
#pragma unroll
        for (int m = 0; m < 2; m++) {
            const int r0 = bm + warpM * 32 + m * 16 + (lane >> 2);
#pragma unroll
            for (int n = 0; n < 8; n++) {
                const int d = n * 4 + d0;
                float2 cs0 = *reinterpret_cast<const float2*>(fc + (size_t)r0 * 64 + d * 2);
                float2 cs1 = *reinterpret_cast<const float2*>(fc + (size_t)(r0 + 8) * 64 + d * 2);
                float x0 = acc[m][n][0], x1 = acc[m][n][1];
                acc[m][n][0] = x0 * cs0.x - x1 * cs0.y;
                acc[m][n][1] = x1 * cs0.x + x0 * cs0.y;
                float y0 = acc[m][n][2], y1 = acc[m][n][3];
                acc[m][n][2] = y0 * cs1.x - y1 * cs1.y;
                acc[m][n][3] = y1 * cs1.x + y0 * cs1.y;
            }
        }
    }

    const int qrow = lane >> 2;
    const int qcol = (lane & 3) * 2;
#pragma unroll
    for (int m = 0; m < 2; m++) {
        const int row0 = bm + warpM * 32 + m * 16 + qrow;
#pragma unroll
        for (int n = 0; n < 8; n++) {
            const int col = bn + warpN * 64 + n * 8 + qcol;
            if (HALF_OUT) {
                __half* C = (__half*)Cv;
                *reinterpret_cast<uint32_t*>(C + (size_t)row0 * N + col) =
                    pack_h2(acc[m][n][0], acc[m][n][1]);
                *reinterpret_cast<uint32_t*>(C + (size_t)(row0 + 8) * N + col) =
                    pack_h2(acc[m][n][2], acc[m][n][3]);
            } else {
                float* C = (float*)Cv;
                *reinterpret_cast<float2*>(C + (size_t)row0 * N + col) =
                    make_float2(acc[m][n][0], acc[m][n][1]);
                *reinterpret_cast<float2*>(C + (size_t)(row0 + 8) * N + col) =
                    make_float2(acc[m][n][2], acc[m][n][3]);
            }
        }
    }
}

// ---------------------------------------------------------------------------
// HMMA flash attention, causal, GQA. Q-tile 128 rows, KV-tile 64.
// 8 warps, warp owns 16 full rows (FA-2, warp-local softmax).
// 4 KV stages (prefetch distance 3 tiles), ONE sync + ONE wait per tile.
// LPT (longest-first) 1D grid.
// ---------------------------------------------------------------------------
#define FK_ROW  144
#define FK_TILE (64 * FK_ROW)
#define FQ_SZ   (128 * FK_ROW)
#define FK_STG  (2 * FK_TILE)
#define FK_NSTG 4
#define FK_SMEM (FQ_SZ + FK_NSTG * FK_STG)     // 92160 B
#define N_QT    (S_LEN / 128)                  // 16

__global__ __launch_bounds__(256, 2) void flash_hmma_kernel(
    const __half* __restrict__ qkvh, __half* __restrict__ Y)
{
    GRID_DEP_SYNC();                     // PDL: wait for GEMM1 grid

    extern __shared__ char sm[];
    const uint32_t sb = smem_to_u32(sm);

    const int bx = blockIdx.x;
    const int qt = (N_QT - 1) - (bx >> 5);     // longest-first
    const int h  = bx & 31;
    const int kh = h >> 2;
    const int q0 = qt * 128;
    const int njt = 2 * qt + 2;                // >= 2 always

    const int tid  = threadIdx.x;
    const int w    = tid >> 5;
    const int lane = tid & 31;

    const float C2 = 0.18033688011112042f;   // (1/8) * log2(e)

    const uint32_t qAddr = (uint32_t)(w * 16 + (lane & 15)) * FK_ROW + (lane >> 4) * 16;
    const uint32_t kAddr = (uint32_t)(((lane >> 4) & 1) * 8 + (lane & 7)) * FK_ROW
                           + ((lane >> 3) & 1) * 16;
    const uint32_t vAddr = (uint32_t)((lane & 7) + ((lane >> 3) & 1) * 8) * FK_ROW
                           + (lane >> 4) * 16;

    auto load_q = [&]() {
#pragma unroll
        for (int i = 0; i < 4; i++) {
            int p = tid + i * 256, row = p >> 3, ch = p & 7;
            cp_async16(sb + (uint32_t)row * FK_ROW + ch * 16,
                       qkvh + (size_t)(q0 + row) * QKV_COLS + h * HD + ch * 8);
        }
    };
    auto load_kv = [&](int s, int jt) {
        const int j0 = jt * 64;
        const uint32_t Kb = sb + FQ_SZ + s * FK_STG;
#pragma unroll
        for (int i = 0; i < 2; i++) {
            int p = tid + i * 256, row = p >> 3, ch = p & 7;
            const __half* base = qkvh + (size_t)(j0 + row) * QKV_COLS + kh * HD + ch * 8;
            cp_async16(Kb + (uint32_t)row * FK_ROW + ch * 16, base + NH * HD);
            cp_async16(Kb + FK_TILE + (uint32_t)row * FK_ROW + ch * 16, base + (NH + NKV) * HD);
        }
    };

    // prologue: Q+kv0 (group 0), kv1 (group 1), kv2 if it exists (group 2)
    load_q(); load_kv(0, 0); cp_commit();
    load_kv(1, 1); cp_commit();
    if (njt > 2) load_kv(2, 2);
    cp_commit();

    uint32_t aQ[4][4];
    float o[8][4];
#pragma unroll
    for (int n = 0; n < 8; n++)
#pragma unroll
        for (int q = 0; q < 4; q++) o[n][q] = 0.f;
    float m2[2] = { -1e30f, -1e30f };
    float l[2]  = { 0.f, 0.f };

    int s = 0;
    for (int jt = 0; jt < njt; jt++) {
        cp_wait2();               // tile jt arrived (2 younger groups pending)
        __syncthreads();
        {
            int s3 = s + 3; if (s3 >= FK_NSTG) s3 -= FK_NSTG;
            if (jt + 3 < njt) load_kv(s3, jt + 3);
            cp_commit();          // one group per iteration (may be empty)
        }
        if (jt == 0) {
#pragma unroll
            for (int kc = 0; kc < 4; kc++) ldsm4(aQ[kc], sb + qAddr + kc * 32);
        }

        const uint32_t Kb = sb + FQ_SZ + s * FK_STG;
        const uint32_t Vb = Kb + FK_TILE;

        float sc[8][4];
#pragma unroll
        for (int n = 0; n < 8; n++)
#pragma unroll
            for (int q = 0; q < 4; q++) sc[n][q] = 0.f;
        {
            uint32_t b0[4], b1[4];
            ldsm4(b0, Kb + kAddr);
#pragma unroll
            for (int t = 0; t < 16; t++) {
                const int p = t >> 2, kc = t & 3;
                uint32_t* bc = (t & 1) ? b1 : b0;
                uint32_t* bn = (t & 1) ? b0 : b1;
                if (t < 15) {
                    const int t2 = t + 1;
                    ldsm4(bn, Kb + kAddr + (uint32_t)(t2 >> 2) * 16 * FK_ROW
                                         + (uint32_t)(t2 & 3) * 32);
                }
                mma16816f16(sc[2 * p + 0], aQ[kc], bc + 0);
                mma16816f16(sc[2 * p + 1], aQ[kc], bc + 2);
            }
        }

        if (jt >= 2 * qt) {
            const int j0 = jt * 64;
            const int rg = q0 + w * 16 + (lane >> 2);
            const int cb = j0 + (lane & 3) * 2;
#pragma unroll
            for (int n = 0; n < 8; n++) {
#pragma unroll
                for (int e = 0; e < 2; e++) {
                    int cg = cb + n * 8 + e;
                    if (cg > rg)     sc[n][e]     = -500.f;
                    if (cg > rg + 8) sc[n][e + 2] = -500.f;
                }
            }
        }

        uint32_t ph[8][2];
        {
            float mr[2], m2n[2], r[2], sum[2];
            u64 NM2[2];
#pragma unroll
            for (int i = 0; i < 2; i++) {
                float m_ = -1e30f;
#pragma unroll
                for (int n = 0; n < 8; n++)
                    m_ = fmaxf(m_, fmaxf(sc[n][2 * i], sc[n][2 * i + 1]));
                mr[i] = m_;
            }
#pragma unroll
            for (int i = 0; i < 2; i++)
                mr[i] = fmaxf(mr[i], __shfl_xor_sync(0xffffffffu, mr[i], 1));
#pragma unroll
            for (int i = 0; i < 2; i++)
                mr[i] = fmaxf(mr[i], __shfl_xor_sync(0xffffffffu, mr[i], 2));
#pragma unroll
            for (int i = 0; i < 2; i++) {
                m2n[i] = fmaxf(m2[i], mr[i] * C2);
                r[i]   = fexp2(m2[i] - m2n[i]);
                m2[i]  = m2n[i];
                NM2[i] = dup2(-m2n[i]);
                sum[i] = 0.f;
            }
            const u64 kSC = dup2(C2);
#pragma unroll
            for (int n = 0; n < 8; n++) {
#pragma unroll
                for (int i = 0; i < 2; i++) {
                    u64 s2  = pk2(sc[n][2 * i], sc[n][2 * i + 1]);
                    u64 arg = fma2_(s2, kSC, NM2[i]);
                    float p0, p1;
                    FEXP2X2(arg, p0, p1);
                    sum[i] += p0 + p1;
                    ph[n][i] = pack_h2(p0, p1);
                }
            }
#pragma unroll
            for (int i = 0; i < 2; i++)
                sum[i] += __shfl_xor_sync(0xffffffffu, sum[i], 1);
#pragma unroll
            for (int i = 0; i < 2; i++)
                sum[i] += __shfl_xor_sync(0xffffffffu, sum[i], 2);
#pragma unroll
            for (int i = 0; i < 2; i++)
                l[i] = l[i] * r[i] + sum[i];
#pragma unroll
            for (int n = 0; n < 8; n++) {
#pragma unroll
                for (int i = 0; i < 2; i++) {
                    o[n][2 * i]     *= r[i];
                    o[n][2 * i + 1] *= r[i];
                }
            }
        }

        {
            uint32_t b0[4], b1[4];
            ldsm4t(b0, Vb + vAddr);
#pragma unroll
            for (int t = 0; t < 16; t++) {
                const int kc = t >> 2, vp = t & 3;
                uint32_t* bc = (t & 1) ? b1 : b0;
                uint32_t* bn = (t & 1) ? b0 : b1;
                if (t < 15) {
                    const int t2 = t + 1;
                    ldsm4t(bn, Vb + vAddr + (uint32_t)(t2 >> 2) * 16 * FK_ROW
                                          + (uint32_t)(t2 & 3) * 32);
                }
                uint32_t a[4] = { ph[2 * kc][0], ph[2 * kc][1],
                                  ph[2 * kc + 1][0], ph[2 * kc + 1][1] };
                mma16816f16(o[2 * vp + 0], a, bc + 0);
                mma16816f16(o[2 * vp + 1], a, bc + 2);
            }
        }

        if (++s == FK_NSTG) s = 0;
    }

    // epilogue: fp16 y
#pragma unroll
    for (int i = 0; i < 2; i++) {
        float inv = 1.f / l[i];
        int row = q0 + w * 16 + (lane >> 2) + 8 * i;
        __half* yr = Y + (size_t)row * H_DIM + h * HD + (lane & 3) * 2;
#pragma unroll
        for (int n = 0; n < 8; n++) {
            __half2 v = __floats2half2_rn(o[n][2 * i] * inv, o[n][2 * i + 1] * inv);
            *reinterpret_cast<__half2*>(yr + n * 8) = v;
        }
    }
}

// ---------------------------------------------------------------------------
// kernel_launch: cvt -> gemm1(+rope) -> flash -> gemm2, chained with PDL.
// ---------------------------------------------------------------------------
template <typename F, typename... Args>
static inline void launch_pdl(F func, dim3 grid, dim3 block, size_t smem,
                              Args... args)
{
    cudaLaunchConfig_t cfg = {};
    cfg.gridDim = grid;
    cfg.blockDim = block;
    cfg.dynamicSmemBytes = smem;
    cfg.stream = 0;
    cudaLaunchAttribute attr[1];
    attr[0].id = cudaLaunchAttributeProgrammaticStreamSerialization;
    attr[0].val.programmaticStreamSerializationAllowed = 1;
    cfg.attrs = attr;
    cfg.numAttrs = 1;
    cudaLaunchKernelEx(&cfg, func, args...);
}

extern "C" void kernel_launch(void* const* d_in, const int* in_sizes, int n_in,
                              void* d_out, int out_size)
{
    const float* x    = (const float*)d_in[0];
    const float* fc   = (const float*)d_in[1];
    const float* Wqkv = (const float*)d_in[3];
    const float* Wo   = (const float*)d_in[4];
    float* out = (float*)d_out;

    __half *qkvh, *ga, *gb, *gc;
    cudaGetSymbolAddress((void**)&qkvh, g_qkvh);
    cudaGetSymbolAddress((void**)&ga, g_a);
    cudaGetSymbolAddress((void**)&gb, g_b);
    cudaGetSymbolAddress((void**)&gc, g_c);

    cudaFuncSetAttribute((const void*)hgemm_kernel<true, true>,
                         cudaFuncAttributeMaxDynamicSharedMemorySize, HM_SMEM);
    cudaFuncSetAttribute((const void*)hgemm_kernel<false, false>,
                         cudaFuncAttributeMaxDynamicSharedMemorySize, HM_SMEM);
    cudaFuncSetAttribute((const void*)flash_hmma_kernel,
                         cudaFuncAttributeMaxDynamicSharedMemorySize, FK_SMEM);

    // 1) fused convert: x, Wqkv, Wo -> fp16 (streaming)
    cvt_all_kernel<<<CVT_BLOCKS, 256>>>(
        (const float4*)x, (const float4*)Wqkv, (const float4*)Wo,
        (uint2*)ga, (uint2*)gb, (uint2*)gc);

    // 2) QKV projection with fused RoPE, fp16 output (PDL after cvt)
    launch_pdl(hgemm_kernel<true, true>,
               dim3(QKV_COLS / 128, S_LEN / 128), dim3(256), HM_SMEM,
               (const __half*)ga, (const __half*)gb, (void*)qkvh,
               (const float*)fc, (int)S_LEN, (int)QKV_COLS, (int)H_DIM);

    // 3) HMMA flash attention (q-tile 128, LPT order, 4 stages) (PDL)
    launch_pdl(flash_hmma_kernel, dim3(N_QT * NH), dim3(256), (size_t)FK_SMEM,
               (const __half*)qkvh, (__half*)ga);

    // 4) output projection, fp32 output (PDL after flash)
    launch_pdl(hgemm_kernel<false, false>,
               dim3(H_DIM / 128, S_LEN / 128), dim3(256), HM_SMEM,
               (const __half*)ga, (const __half*)gc, (void*)out,
               (const float*)nullptr, (int)S_LEN, (int)H_DIM, (int)H_DIM);
}

// round 17
// speedup vs baseline: 1.0614x; 1.0079x over previous
#include <cuda_runtime.h>
#include <cuda_fp16.h>
#include <cstdint>

// Problem constants (fixed by the dataset)
#define S_LEN 2048
#define H_DIM 2048
#define NH    32
#define NKV   8
#define HD    64
#define QKV_COLS ((NH + 2*NKV) * HD)   // 3072

// ---------------------------------------------------------------------------
// Scratch (allocation-free rule: __device__ globals)
// ---------------------------------------------------------------------------
__device__ __align__(16) __half g_qkvh[(size_t)S_LEN * QKV_COLS]; // 12 MB
__device__ __align__(16) __half g_a[(size_t)S_LEN * H_DIM];       // 8 MB (x, then y)
__device__ __align__(16) __half g_b[(size_t)QKV_COLS * H_DIM];    // 12 MB (Wqkv)
__device__ __align__(16) __half g_c[(size_t)H_DIM * H_DIM];       // 8 MB (Wo)

// ---------------------------------------------------------------------------
// PTX helpers (sm_80+ ISA; tcgen05 rejected by plain-sm_103 ptxas)
// ---------------------------------------------------------------------------
__device__ __forceinline__ uint32_t smem_to_u32(const void* p) {
    uint32_t a;
    asm("{ .reg .u64 t; cvta.to.shared.u64 t, %1; cvt.u32.u64 %0, t; }"
        : "=r"(a) : "l"(p));
    return a;
}
__device__ __forceinline__ void cp_async16(uint32_t smem, const void* gptr) {
    asm volatile("cp.async.cg.shared.global [%0], [%1], 16;"
                 :: "r"(smem), "l"(__cvta_generic_to_global(gptr)) : "memory");
}
__device__ __forceinline__ void cp_commit() {
    asm volatile("cp.async.commit_group;" ::: "memory");
}
__device__ __forceinline__ void cp_wait1() {
    asm volatile("cp.async.wait_group 1;" ::: "memory");
}
__device__ __forceinline__ void cp_wait2() {
    asm volatile("cp.async.wait_group 2;" ::: "memory");
}
__device__ __forceinline__ void ldsm4(uint32_t* r, uint32_t addr) {
    asm volatile("ldmatrix.sync.aligned.m8n8.x4.shared.b16 {%0,%1,%2,%3}, [%4];"
                 : "=r"(r[0]), "=r"(r[1]), "=r"(r[2]), "=r"(r[3]) : "r"(addr));
}
__device__ __forceinline__ void ldsm4t(uint32_t* r, uint32_t addr) {
    asm volatile("ldmatrix.sync.aligned.m8n8.x4.trans.shared.b16 {%0,%1,%2,%3}, [%4];"
                 : "=r"(r[0]), "=r"(r[1]), "=r"(r[2]), "=r"(r[3]) : "r"(addr));
}
__device__ __forceinline__ void mma16816f16(float* c, const uint32_t* a, const uint32_t* b) {
    asm volatile(
        "mma.sync.aligned.m16n8k16.row.col.f32.f16.f16.f32 "
        "{%0,%1,%2,%3}, {%4,%5,%6,%7}, {%8,%9}, {%0,%1,%2,%3};"
        : "+f"(c[0]), "+f"(c[1]), "+f"(c[2]), "+f"(c[3])
        : "r"(a[0]), "r"(a[1]), "r"(a[2]), "r"(a[3]), "r"(b[0]), "r"(b[1]));
}
__device__ __forceinline__ uint32_t pack_h2(float a, float b) {
    __half2 h = __floats2half2_rn(a, b);
    return *reinterpret_cast<uint32_t*>(&h);
}

// ---- packed f32x2 ops (Blackwell base ISA) ----
typedef unsigned long long u64;
__device__ __forceinline__ u64 pk2(float a, float b) {
    u64 r; asm("mov.b64 %0, {%1, %2};" : "=l"(r) : "f"(a), "f"(b)); return r;
}
__device__ __forceinline__ void upk2(u64 v, float& a, float& b) {
    asm("mov.b64 {%0, %1}, %2;" : "=f"(a), "=f"(b) : "l"(v));
}
__device__ __forceinline__ u64 add2_(u64 a, u64 b) {
    u64 r; asm("add.rn.f32x2 %0, %1, %2;" : "=l"(r) : "l"(a), "l"(b)); return r;
}
__device__ __forceinline__ u64 fma2_(u64 a, u64 b, u64 c) {
    u64 r; asm("fma.rn.f32x2 %0, %1, %2, %3;" : "=l"(r) : "l"(a), "l"(b), "l"(c)); return r;
}
__device__ __forceinline__ u64 dup2(float x) {
    unsigned int b = __float_as_uint(x);
    return ((u64)b << 32) | b;
}

// Scalar fast 2^d (clamped; per-pass rescale factor only).
__device__ __forceinline__ float fexp2(float d) {
    d = fmaxf(d, -80.0f);
    float t  = d + 12582912.0f;
    float nf = t - 12582912.0f;
    float f  = d - nf;
    int   n  = __float_as_int(t) - 0x4B400000;
    float p  = 9.6181291e-3f;
    p = fmaf(p, f, 5.5504108664e-2f);
    p = fmaf(p, f, 2.4022650696e-1f);
    p = fmaf(p, f, 6.9314718056e-1f);
    p = fmaf(p, f, 1.0f);
    return __int_as_float(__float_as_int(p) + (n << 23));
}

// Packed 2^(a0), 2^(a1); args in [-126, 0] (mask sentinel -500 guarantees).
#define FEXP2X2(arg, r0, r1) do {                                           \
    const u64 _kMAG  = dup2(12582912.0f);                                   \
    const u64 _kNEG1 = dup2(-1.0f);                                         \
    u64 _t  = add2_(arg, _kMAG);                                            \
    u64 _nf = add2_(_t, dup2(-12582912.0f));                                \
    u64 _f  = fma2_(_nf, _kNEG1, arg);                                      \
    u64 _p  = fma2_(dup2(9.6181291e-3f), _f, dup2(5.5504108664e-2f));       \
    _p = fma2_(_p, _f, dup2(2.4022650696e-1f));                             \
    _p = fma2_(_p, _f, dup2(6.9314718056e-1f));                             \
    _p = fma2_(_p, _f, dup2(1.0f));                                         \
    float _t0, _t1, _p0, _p1;                                               \
    upk2(_t, _t0, _t1);                                                     \
    upk2(_p, _p0, _p1);                                                     \
    int _n0 = (__float_as_int(_t0) - 0x4B400000) << 23;                     \
    int _n1 = (__float_as_int(_t1) - 0x4B400000) << 23;                     \
    r0 = __int_as_float(__float_as_int(_p0) + _n0);                         \
    r1 = __int_as_float(__float_as_int(_p1) + _n1);                         \
} while (0)

#if defined(__CUDA_ARCH__) && __CUDA_ARCH__ >= 900
#define GRID_DEP_SYNC() cudaGridDependencySynchronize()
#define GRID_TRIGGER()  cudaTriggerProgrammaticLaunchCompletion()
#else
#define GRID_DEP_SYNC()
#define GRID_TRIGGER()
#endif

// ---------------------------------------------------------------------------
// Fused fp32 -> fp16 convert for x, Wqkv, Wo. Streaming (evict-first).
// ---------------------------------------------------------------------------
#define N4_X  (S_LEN * H_DIM / 4)
#define N4_WQ (QKV_COLS * H_DIM / 4)
#define N4_WO (H_DIM * H_DIM / 4)
#define N4_ALL (N4_X + N4_WQ + N4_WO)
#define CVT_BLOCKS (N4_ALL / 1024)

__global__ __launch_bounds__(256) void cvt_all_kernel(
    const float4* __restrict__ x, const float4* __restrict__ wq,
    const float4* __restrict__ wo,
    uint2* __restrict__ ox, uint2* __restrict__ owq, uint2* __restrict__ owo)
{
    const size_t base = (size_t)blockIdx.x * 1024;
    const float4* in;
    uint2* out;
    size_t j0;
    if (base < N4_X)                      { in = x;  out = ox;  j0 = base; }
    else if (base < (size_t)N4_X + N4_WQ) { in = wq; out = owq; j0 = base - N4_X; }
    else                                  { in = wo; out = owo; j0 = base - N4_X - N4_WQ; }

    const size_t t = j0 + threadIdx.x;
    float4 f0 = __ldcs(in + t);
    float4 f1 = __ldcs(in + t + 256);
    float4 f2 = __ldcs(in + t + 512);
    float4 f3 = __ldcs(in + t + 768);
    __stcs(out + t,       make_uint2(pack_h2(f0.x, f0.y), pack_h2(f0.z, f0.w)));
    __stcs(out + t + 256, make_uint2(pack_h2(f1.x, f1.y), pack_h2(f1.z, f1.w)));
    __stcs(out + t + 512, make_uint2(pack_h2(f2.x, f2.y), pack_h2(f2.z, f2.w)));
    __stcs(out + t + 768, make_uint2(pack_h2(f3.x, f3.y), pack_h2(f3.z, f3.w)));
    GRID_TRIGGER();
}

// ---------------------------------------------------------------------------
// HMMA TN GEMM, fp16 in, templated output (fp32/fp16) + optional fused RoPE.
// CTA 128x128, BK=64, 3-stage cp.async pipeline. Validated R9/R10 mainloop.
// ---------------------------------------------------------------------------
#define HM_ROWB   144
#define HM_TILE_B (128 * HM_ROWB)            // 18432 B
#define HM_STAGE  (2 * HM_TILE_B)            // 36864 B
#define HM_SMEM   (3 * HM_STAGE)             // 110592 B

template <bool HALF_OUT, bool ROPE>
__global__ __launch_bounds__(256, 2) void hgemm_kernel(
    const __half* __restrict__ A, const __half* __restrict__ B,
    void* __restrict__ Cv, const float* __restrict__ fc, int M, int N, int K)
{
    GRID_DEP_SYNC();                     // PDL: wait for producer grid

    extern __shared__ char smem[];
    const uint32_t sbase = smem_to_u32(smem);

    const int tid  = threadIdx.x;
    const int wid  = tid >> 5;
    const int lane = tid & 31;
    const int warpM = wid >> 1;
    const int warpN = wid & 1;
    const int bm = blockIdx.y * 128;
    const int bn = blockIdx.x * 128;

    const int ldrow = tid >> 3;
    const int ldch  = (tid & 7) * 16;
    const __half* gA0 = A + (size_t)(bm + ldrow) * K + (ldch >> 1);
    const __half* gB0 = B + (size_t)(bn + ldrow) * K + (ldch >> 1);

    const uint32_t aAddrBase =
        (uint32_t)(warpM * 32 + (lane & 15)) * HM_ROWB + (lane >> 4) * 16;
    const uint32_t bAddrBase =
        (uint32_t)(warpN * 64 + ((lane >> 4) & 1) * 8 + (lane & 7)) * HM_ROWB
        + ((lane >> 3) & 1) * 16;

    float acc[2][8][4];
#pragma unroll
    for (int m = 0; m < 2; m++)
#pragma unroll
        for (int n = 0; n < 8; n++)
#pragma unroll
            for (int q = 0; q < 4; q++) acc[m][n][q] = 0.f;

    const int nchunk = K / 64;

    auto load_stage = [&](int s, int c) {
        const uint32_t st = sbase + s * HM_STAGE;
        const int k0 = c * 64;
#pragma unroll
        for (int i = 0; i < 4; i++) {
            const uint32_t so = (uint32_t)(ldrow + 32 * i) * HM_ROWB + ldch;
            cp_async16(st + so, gA0 + (size_t)(32 * i) * K + k0);
            cp_async16(st + HM_TILE_B + so, gB0 + (size_t)(32 * i) * K + k0);
        }
    };

    load_stage(0, 0); cp_commit();
    load_stage(1, 1); cp_commit();

    int s = 0;
    for (int c = 0; c < nchunk; c++) {
        cp_wait1();
        __syncthreads();
        {
            int s2 = s + 2; if (s2 >= 3) s2 -= 3;
            if (c + 2 < nchunk) load_stage(s2, c + 2);
            cp_commit();
        }

        const uint32_t st = sbase + s * HM_STAGE;
        const uint32_t sA = st + aAddrBase;
        const uint32_t sB = st + HM_TILE_B + bAddrBase;

#pragma unroll
        for (int ks = 0; ks < 4; ks++) {
            const uint32_t ko = ks * 32;
            uint32_t a[2][4];
            ldsm4(a[0], sA + ko);
            ldsm4(a[1], sA + 16 * HM_ROWB + ko);
            uint32_t b0[4], b1[4];
            ldsm4(b0, sB + ko);
#pragma unroll
            for (int p = 0; p < 4; p++) {
                uint32_t* bc = (p & 1) ? b1 : b0;
                uint32_t* bn2 = (p & 1) ? b0 : b1;
                if (p < 3)
                    ldsm4(bn2, sB + (uint32_t)(p + 1) * 16 * HM_ROWB + ko);
#pragma unroll
                for (int m = 0; m < 2; m++) {
                    mma16816f16(acc[m][2 * p + 0], a[m], bc + 0);
                    mma16816f16(acc[m][2 * p + 1], a[m], bc + 2);
                }
            }
        }
        if (++s == 3) s = 0;
    }

    // fused RoPE (uniform per CTA: q/k head cols are [0,2560), 128-aligned)
    if (ROPE && bn < NH * HD + NKV * HD) {
        const int d0 = lane & 3;
#pragma unroll
        for (int m = 0; m < 2; m++) {
            const int r0 = bm + warpM * 32 + m * 16 + (lane >> 2);
#pragma unroll
            for (int n = 0; n < 8; n++) {
                const int d = n * 4 + d0;
                float2 cs0 = *reinterpret_cast<const float2*>(fc + (size_t)r0 * 64 + d * 2);
                float2 cs1 = *reinterpret_cast<const float2*>(fc + (size_t)(r0 + 8) * 64 + d * 2);
                float x0 = acc[m][n][0], x1 = acc[m][n][1];
                acc[m][n][0] = x0 * cs0.x - x1 * cs0.y;
                acc[m][n][1] = x1 * cs0.x + x0 * cs0.y;
                float y0 = acc[m][n][2], y1 = acc[m][n][3];
                acc[m][n][2] = y0 * cs1.x - y1 * cs1.y;
                acc[m][n][3] = y1 * cs1.x + y0 * cs1.y;
            }
        }
    }

    const int qrow = lane >> 2;
    const int qcol = (lane & 3) * 2;
#pragma unroll
    for (int m = 0; m < 2; m++) {
        const int row0 = bm + warpM * 32 + m * 16 + qrow;
#pragma unroll
        for (int n = 0; n < 8; n++) {
            const int col = bn + warpN * 64 + n * 8 + qcol;
            if (HALF_OUT) {
                __half* C = (__half*)Cv;
                *reinterpret_cast<uint32_t*>(C + (size_t)row0 * N + col) =
                    pack_h2(acc[m][n][0], acc[m][n][1]);
                *reinterpret_cast<uint32_t*>(C + (size_t)(row0 + 8) * N + col) =
                    pack_h2(acc[m][n][2], acc[m][n][3]);
            } else {
                float* C = (float*)Cv;
                *reinterpret_cast<float2*>(C + (size_t)row0 * N + col) =
                    make_float2(acc[m][n][0], acc[m][n][1]);
                *reinterpret_cast<float2*>(C + (size_t)(row0 + 8) * N + col) =
                    make_float2(acc[m][n][2], acc[m][n][3]);
            }
        }
    }
    GRID_TRIGGER();
}

// ---------------------------------------------------------------------------
// HMMA flash attention, causal, GQA. Q-tile 128 rows, KV-tile 64.
// 8 warps, warp owns 16 full rows (FA-2, warp-local softmax).
// 4 KV stages, ONE sync + ONE wait per tile. LPT (longest-first) 1D grid.
// Last kv-tile: warps 0-3 (rows < q0+64 < all cols) are fully masked — their
// QK mma / softmax / PV mma are a provable no-op and are skipped.
// ---------------------------------------------------------------------------
#define FK_ROW  144
#define FK_TILE (64 * FK_ROW)
#define FQ_SZ   (128 * FK_ROW)
#define FK_STG  (2 * FK_TILE)
#define FK_NSTG 4
#define FK_SMEM (FQ_SZ + FK_NSTG * FK_STG)     // 92160 B
#define N_QT    (S_LEN / 128)                  // 16

__global__ __launch_bounds__(256, 2) void flash_hmma_kernel(
    const __half* __restrict__ qkvh, __half* __restrict__ Y)
{
    GRID_DEP_SYNC();                     // PDL: wait for GEMM1 grid

    extern __shared__ char sm[];
    const uint32_t sb = smem_to_u32(sm);

    const int bx = blockIdx.x;
    const int qt = (N_QT - 1) - (bx >> 5);     // longest-first
    const int h  = bx & 31;
    const int kh = h >> 2;
    const int q0 = qt * 128;
    const int njt = 2 * qt + 2;                // >= 2 always

    const int tid  = threadIdx.x;
    const int w    = tid >> 5;
    const int lane = tid & 31;

    const float C2 = 0.18033688011112042f;   // (1/8) * log2(e)

    const uint32_t qAddr = (uint32_t)(w * 16 + (lane & 15)) * FK_ROW + (lane >> 4) * 16;
    const uint32_t kAddr = (uint32_t)(((lane >> 4) & 1) * 8 + (lane & 7)) * FK_ROW
                           + ((lane >> 3) & 1) * 16;
    const uint32_t vAddr = (uint32_t)((lane & 7) + ((lane >> 3) & 1) * 8) * FK_ROW
                           + (lane >> 4) * 16;

    auto load_q = [&]() {
#pragma unroll
        for (int i = 0; i < 4; i++) {
            int p = tid + i * 256, row = p >> 3, ch = p & 7;
            cp_async16(sb + (uint32_t)row * FK_ROW + ch * 16,
                       qkvh + (size_t)(q0 + row) * QKV_COLS + h * HD + ch * 8);
        }
    };
    auto load_kv = [&](int s, int jt) {
        const int j0 = jt * 64;
        const uint32_t Kb = sb + FQ_SZ + s * FK_STG;
#pragma unroll
        for (int i = 0; i < 2; i++) {
            int p = tid + i * 256, row = p >> 3, ch = p & 7;
            const __half* base = qkvh + (size_t)(j0 + row) * QKV_COLS + kh * HD + ch * 8;
            cp_async16(Kb + (uint32_t)row * FK_ROW + ch * 16, base + NH * HD);
            cp_async16(Kb + FK_TILE + (uint32_t)row * FK_ROW + ch * 16, base + (NH + NKV) * HD);
        }
    };

    // prologue: Q+kv0 (group 0), kv1 (group 1), kv2 if it exists (group 2)
    load_q(); load_kv(0, 0); cp_commit();
    load_kv(1, 1); cp_commit();
    if (njt > 2) load_kv(2, 2);
    cp_commit();

    uint32_t aQ[4][4];
    float o[8][4];
#pragma unroll
    for (int n = 0; n < 8; n++)
#pragma unroll
        for (int q = 0; q < 4; q++) o[n][q] = 0.f;
    float m2[2] = { -1e30f, -1e30f };
    float l[2]  = { 0.f, 0.f };

    int s = 0;
    for (int jt = 0; jt < njt; jt++) {
        cp_wait2();
        __syncthreads();
        {
            int s3 = s + 3; if (s3 >= FK_NSTG) s3 -= FK_NSTG;
            if (jt + 3 < njt) load_kv(s3, jt + 3);
            cp_commit();
        }
        if (jt == 0) {
#pragma unroll
            for (int kc = 0; kc < 4; kc++) ldsm4(aQ[kc], sb + qAddr + kc * 32);
        }

        // last kv-tile: warps 0-3 cover rows < q0+64, all cols >= q0+64 —
        // fully masked; P == 0 so the whole tile body is a no-op for them.
        if (jt == njt - 1 && w < 4) {
            if (++s == FK_NSTG) s = 0;
            continue;
        }

        const uint32_t Kb = sb + FQ_SZ + s * FK_STG;
        const uint32_t Vb = Kb + FK_TILE;

        float sc[8][4];
#pragma unroll
        for (int n = 0; n < 8; n++)
#pragma unroll
            for (int q = 0; q < 4; q++) sc[n][q] = 0.f;
        {
            uint32_t b0[4], b1[4];
            ldsm4(b0, Kb + kAddr);
#pragma unroll
            for (int t = 0; t < 16; t++) {
                const int p = t >> 2, kc = t & 3;
                uint32_t* bc = (t & 1) ? b1 : b0;
                uint32_t* bn = (t & 1) ? b0 : b1;
                if (t < 15) {
                    const int t2 = t + 1;
                    ldsm4(bn, Kb + kAddr + (uint32_t)(t2 >> 2) * 16 * FK_ROW
                                         + (uint32_t)(t2 & 3) * 32);
                }
                mma16816f16(sc[2 * p + 0], aQ[kc], bc + 0);
                mma16816f16(sc[2 * p + 1], aQ[kc], bc + 2);
            }
        }

        if (jt >= 2 * qt) {
            const int j0 = jt * 64;
            const int rg = q0 + w * 16 + (lane >> 2);
            const int cb = j0 + (lane & 3) * 2;
#pragma unroll
            for (int n = 0; n < 8; n++) {
#pragma unroll
                for (int e = 0; e < 2; e++) {
                    int cg = cb + n * 8 + e;
                    if (cg > rg)     sc[n][e]     = -500.f;
                    if (cg > rg + 8) sc[n][e + 2] = -500.f;
                }
            }
        }

        uint32_t ph[8][2];
        {
            float mr[2], m2n[2], r[2], sum[2];
            u64 NM2[2];
#pragma unroll
            for (int i = 0; i < 2; i++) {
                float m_ = -1e30f;
#pragma unroll
                for (int n = 0; n < 8; n++)
                    m_ = fmaxf(m_, fmaxf(sc[n][2 * i], sc[n][2 * i + 1]));
                mr[i] = m_;
            }
#pragma unroll
            for (int i = 0; i < 2; i++)
                mr[i] = fmaxf(mr[i], __shfl_xor_sync(0xffffffffu, mr[i], 1));
#pragma unroll
            for (int i = 0; i < 2; i++)
                mr[i] = fmaxf(mr[i], __shfl_xor_sync(0xffffffffu, mr[i], 2));
#pragma unroll
            for (int i = 0; i < 2; i++) {
                m2n[i] = fmaxf(m2[i], mr[i] * C2);
                r[i]   = fexp2(m2[i] - m2n[i]);
                m2[i]  = m2n[i];
                NM2[i] = dup2(-m2n[i]);
                sum[i] = 0.f;
            }
            const u64 kSC = dup2(C2);
#pragma unroll
            for (int n = 0; n < 8; n++) {
#pragma unroll
                for (int i = 0; i < 2; i++) {
                    u64 s2  = pk2(sc[n][2 * i], sc[n][2 * i + 1]);
                    u64 arg = fma2_(s2, kSC, NM2[i]);
                    float p0, p1;
                    FEXP2X2(arg, p0, p1);
                    sum[i] += p0 + p1;
                    ph[n][i] = pack_h2(p0, p1);
                }
            }
#pragma unroll
            for (int i = 0; i < 2; i++)
                sum[i] += __shfl_xor_sync(0xffffffffu, sum[i], 1);
#pragma unroll
            for (int i = 0; i < 2; i++)
                sum[i] += __shfl_xor_sync(0xffffffffu, sum[i], 2);
#pragma unroll
            for (int i = 0; i < 2; i++)
                l[i] = l[i] * r[i] + sum[i];
#pragma unroll
            for (int n = 0; n < 8; n++) {
#pragma unroll
                for (int i = 0; i < 2; i++) {
                    o[n][2 * i]     *= r[i];
                    o[n][2 * i + 1] *= r[i];
                }
            }
        }

        {
            uint32_t b0[4], b1[4];
            ldsm4t(b0, Vb + vAddr);
#pragma unroll
            for (int t = 0; t < 16; t++) {
                const int kc = t >> 2, vp = t & 3;
                uint32_t* bc = (t & 1) ? b1 : b0;
                uint32_t* bn = (t & 1) ? b0 : b1;
                if (t < 15) {
                    const int t2 = t + 1;
                    ldsm4t(bn, Vb + vAddr + (uint32_t)(t2 >> 2) * 16 * FK_ROW
                                          + (uint32_t)(t2 & 3) * 32);
                }
                uint32_t a[4] = { ph[2 * kc][0], ph[2 * kc][1],
                                  ph[2 * kc + 1][0], ph[2 * kc + 1][1] };
                mma16816f16(o[2 * vp + 0], a, bc + 0);
                mma16816f16(o[2 * vp + 1], a, bc + 2);
            }
        }

        if (++s == FK_NSTG) s = 0;
    }

    // epilogue: fp16 y
#pragma unroll
    for (int i = 0; i < 2; i++) {
        float inv = 1.f / l[i];
        int row = q0 + w * 16 + (lane >> 2) + 8 * i;
        __half* yr = Y + (size_t)row * H_DIM + h * HD + (lane & 3) * 2;
#pragma unroll
        for (int n = 0; n < 8; n++) {
            __half2 v = __floats2half2_rn(o[n][2 * i] * inv, o[n][2 * i + 1] * inv);
            *reinterpret_cast<__half2*>(yr + n * 8) = v;
        }
    }
    GRID_TRIGGER();
}

// ---------------------------------------------------------------------------
// kernel_launch: cvt -> gemm1(+rope) -> flash -> gemm2, chained with PDL.
// ---------------------------------------------------------------------------
template <typename F, typename... Args>
static inline void launch_pdl(F func, dim3 grid, dim3 block, size_t smem,
                              Args... args)
{
    cudaLaunchConfig_t cfg = {};
    cfg.gridDim = grid;
    cfg.blockDim = block;
    cfg.dynamicSmemBytes = smem;
    cfg.stream = 0;
    cudaLaunchAttribute attr[1];
    attr[0].id = cudaLaunchAttributeProgrammaticStreamSerialization;
    attr[0].val.programmaticStreamSerializationAllowed = 1;
    cfg.attrs = attr;
    cfg.numAttrs = 1;
    cudaLaunchKernelEx(&cfg, func, args...);
}

extern "C" void kernel_launch(void* const* d_in, const int* in_sizes, int n_in,
                              void* d_out, int out_size)
{
    const float* x    = (const float*)d_in[0];
    const float* fc   = (const float*)d_in[1];
    const float* Wqkv = (const float*)d_in[3];
    const float* Wo   = (const float*)d_in[4];
    float* out = (float*)d_out;

    __half *qkvh, *ga, *gb, *gc;
    cudaGetSymbolAddress((void**)&qkvh, g_qkvh);
    cudaGetSymbolAddress((void**)&ga, g_a);
    cudaGetSymbolAddress((void**)&gb, g_b);
    cudaGetSymbolAddress((void**)&gc, g_c);

    cudaFuncSetAttribute((const void*)hgemm_kernel<true, true>,
                         cudaFuncAttributeMaxDynamicSharedMemorySize, HM_SMEM);
    cudaFuncSetAttribute((const void*)hgemm_kernel<false, false>,
                         cudaFuncAttributeMaxDynamicSharedMemorySize, HM_SMEM);
    cudaFuncSetAttribute((const void*)flash_hmma_kernel,
                         cudaFuncAttributeMaxDynamicSharedMemorySize, FK_SMEM);

    // 1) fused convert: x, Wqkv, Wo -> fp16 (streaming)
    cvt_all_kernel<<<CVT_BLOCKS, 256>>>(
        (const float4*)x, (const float4*)Wqkv, (const float4*)Wo,
        (uint2*)ga, (uint2*)gb, (uint2*)gc);

    // 2) QKV projection with fused RoPE, fp16 output (PDL after cvt)
    launch_pdl(hgemm_kernel<true, true>,
               dim3(QKV_COLS / 128, S_LEN / 128), dim3(256), HM_SMEM,
               (const __half*)ga, (const __half*)gb, (void*)qkvh,
               (const float*)fc, (int)S_LEN, (int)QKV_COLS, (int)H_DIM);

    // 3) HMMA flash attention (q-tile 128, LPT order, 4 stages) (PDL)
    launch_pdl(flash_hmma_kernel, dim3(N_QT * NH), dim3(256), (size_t)FK_SMEM,
               (const __half*)qkvh, (__half*)ga);

    // 4) output projection, fp32 output (PDL after flash)
    launch_pdl(hgemm_kernel<false, false>,
               dim3(H_DIM / 128, S_LEN / 128), dim3(256), HM_SMEM,
               (const __half*)ga, (const __half*)gc, (void*)out,
               (const float*)nullptr, (int)S_LEN, (int)H_DIM, (int)H_DIM);
}